// round 2
// baseline (speedup 1.0000x reference)
#include <cuda_runtime.h>
#include <cuda_bf16.h>

// CumAvgPool1d: y[..., t] = cumsum(x)[..., t] / (t+1)
// x: (8, 512, 16384) fp32 -> 4096 rows of T=16384.
// One CTA (1024 threads) per row. Each thread owns 16 contiguous floats
// (4 x float4), does a register-resident local inclusive scan, then a
// shuffle+smem block scan of the 1024 per-thread totals, then writes
// (offset + local) * 1/(t+1) back with float4 stores.

constexpr int T_LEN   = 16384;
constexpr int THREADS = 1024;
// per-thread elements = T_LEN / THREADS = 16 = 4 float4

__global__ void __launch_bounds__(THREADS, 1)
cumavg_kernel(const float4* __restrict__ x, float4* __restrict__ y)
{
    const int row  = blockIdx.x;
    const int tid  = threadIdx.x;
    const int lane = tid & 31;
    const int warp = tid >> 5;

    const size_t base = (size_t)row * (T_LEN / 4);   // in float4 units
    const float4* px = x + base + (size_t)tid * 4;

    // Load 16 contiguous floats (4 x float4)
    float4 v0 = px[0];
    float4 v1 = px[1];
    float4 v2 = px[2];
    float4 v3 = px[3];

    // Thread-local inclusive scan, overwriting in place
    float run = 0.0f;
    run += v0.x; v0.x = run;  run += v0.y; v0.y = run;
    run += v0.z; v0.z = run;  run += v0.w; v0.w = run;
    run += v1.x; v1.x = run;  run += v1.y; v1.y = run;
    run += v1.z; v1.z = run;  run += v1.w; v1.w = run;
    run += v2.x; v2.x = run;  run += v2.y; v2.y = run;
    run += v2.z; v2.z = run;  run += v2.w; v2.w = run;
    run += v3.x; v3.x = run;  run += v3.y; v3.y = run;
    run += v3.z; v3.z = run;  run += v3.w; v3.w = run;
    // run = this thread's total

    // Warp-level inclusive scan of per-thread totals
    float wval = run;
    #pragma unroll
    for (int d = 1; d < 32; d <<= 1) {
        float n = __shfl_up_sync(0xffffffffu, wval, d);
        if (lane >= d) wval += n;
    }

    __shared__ float warp_sums[32];
    if (lane == 31) warp_sums[warp] = wval;
    __syncthreads();

    // Warp 0 scans the 32 warp totals
    if (warp == 0) {
        float w = warp_sums[lane];
        #pragma unroll
        for (int d = 1; d < 32; d <<= 1) {
            float n = __shfl_up_sync(0xffffffffu, w, d);
            if (lane >= d) w += n;
        }
        warp_sums[lane] = w;
    }
    __syncthreads();

    // Exclusive prefix for this thread
    float offset = (wval - run);                 // exclusive within warp
    if (warp > 0) offset += warp_sums[warp - 1]; // preceding warps

    // Scale by 1/(t+1) and store
    const int t0 = tid * 16;   // global index of this thread's first element
    float4 o;

    o.x = (offset + v0.x) * __fdividef(1.0f, (float)(t0 + 1));
    o.y = (offset + v0.y) * __fdividef(1.0f, (float)(t0 + 2));
    o.z = (offset + v0.z) * __fdividef(1.0f, (float)(t0 + 3));
    o.w = (offset + v0.w) * __fdividef(1.0f, (float)(t0 + 4));
    float4* py = y + base + (size_t)tid * 4;
    py[0] = o;

    o.x = (offset + v1.x) * __fdividef(1.0f, (float)(t0 + 5));
    o.y = (offset + v1.y) * __fdividef(1.0f, (float)(t0 + 6));
    o.z = (offset + v1.z) * __fdividef(1.0f, (float)(t0 + 7));
    o.w = (offset + v1.w) * __fdividef(1.0f, (float)(t0 + 8));
    py[1] = o;

    o.x = (offset + v2.x) * __fdividef(1.0f, (float)(t0 + 9));
    o.y = (offset + v2.y) * __fdividef(1.0f, (float)(t0 + 10));
    o.z = (offset + v2.z) * __fdividef(1.0f, (float)(t0 + 11));
    o.w = (offset + v2.w) * __fdividef(1.0f, (float)(t0 + 12));
    py[2] = o;

    o.x = (offset + v3.x) * __fdividef(1.0f, (float)(t0 + 13));
    o.y = (offset + v3.y) * __fdividef(1.0f, (float)(t0 + 14));
    o.z = (offset + v3.z) * __fdividef(1.0f, (float)(t0 + 15));
    o.w = (offset + v3.w) * __fdividef(1.0f, (float)(t0 + 16));
    py[3] = o;
}

extern "C" void kernel_launch(void* const* d_in, const int* in_sizes, int n_in,
                              void* d_out, int out_size)
{
    const float* x = (const float*)d_in[0];
    float*       y = (float*)d_out;
    const int total = in_sizes[0];
    const int rows  = total / T_LEN;   // 4096 for the reference shape

    cumavg_kernel<<<rows, THREADS>>>((const float4*)x, (float4*)y);
}

// round 3
// speedup vs baseline: 1.0407x; 1.0407x over previous
#include <cuda_runtime.h>
#include <cuda_bf16.h>

// CumAvgPool1d: y[..., t] = cumsum(x)[..., t] / (t+1)
// x: (8, 512, 16384) fp32 -> 4096 rows of T=16384.
//
// R2: pipelined chunked scan. One CTA (1024 threads) per row, row split into
// 4 chunks of 4096 elems (1 float4 per thread per chunk). Loads for chunk c+1
// are issued before the barriers/stores of chunk c so HBM reads and writes
// overlap instead of alternating in bursts. Running carry propagates the
// block prefix across chunks; warp-sum smem is double-buffered on chunk
// parity to avoid an extra WAR barrier.

constexpr int T_LEN   = 16384;
constexpr int THREADS = 1024;
constexpr int NCHUNK  = 4;                    // 4 * 1024 * 4 = 16384
constexpr int CHUNK_F4 = THREADS;             // float4 per chunk

__global__ void __launch_bounds__(THREADS, 1)
cumavg_kernel(const float4* __restrict__ x, float4* __restrict__ y)
{
    const int row  = blockIdx.x;
    const int tid  = threadIdx.x;
    const int lane = tid & 31;
    const int warp = tid >> 5;

    const size_t base = (size_t)row * (T_LEN / 4);   // float4 units
    const float4* px = x + base;
    float4*       py = y + base;

    __shared__ float wsum[2][32];

    float carry = 0.0f;

    // prefetch chunk 0
    float4 cur = px[tid];

    #pragma unroll
    for (int c = 0; c < NCHUNK; ++c) {
        // issue next chunk's load ASAP (overlaps with scan + stores below)
        float4 nxt;
        if (c < NCHUNK - 1) nxt = px[(c + 1) * CHUNK_F4 + tid];

        // thread-local inclusive scan of 4 elements
        float r = cur.x;          cur.x = r;
        r += cur.y;               cur.y = r;
        r += cur.z;               cur.z = r;
        r += cur.w;               cur.w = r;

        // warp inclusive scan of per-thread totals
        float wval = r;
        #pragma unroll
        for (int d = 1; d < 32; d <<= 1) {
            float n = __shfl_up_sync(0xffffffffu, wval, d);
            if (lane >= d) wval += n;
        }

        const int pb = c & 1;
        if (lane == 31) wsum[pb][warp] = wval;
        __syncthreads();

        if (warp == 0) {
            float w = wsum[pb][lane];
            #pragma unroll
            for (int d = 1; d < 32; d <<= 1) {
                float n = __shfl_up_sync(0xffffffffu, w, d);
                if (lane >= d) w += n;
            }
            wsum[pb][lane] = w;
        }
        __syncthreads();

        float off = carry + (wval - r);            // exclusive within warp + prior chunks
        if (warp > 0) off += wsum[pb][warp - 1];   // preceding warps
        const float total = wsum[pb][31];          // whole-chunk sum (broadcast)

        // scale by 1/(t+1) and store
        const int t0 = c * (CHUNK_F4 * 4) + tid * 4;
        float4 o;
        o.x = (off + cur.x) * __fdividef(1.0f, (float)(t0 + 1));
        o.y = (off + cur.y) * __fdividef(1.0f, (float)(t0 + 2));
        o.z = (off + cur.z) * __fdividef(1.0f, (float)(t0 + 3));
        o.w = (off + cur.w) * __fdividef(1.0f, (float)(t0 + 4));
        py[c * CHUNK_F4 + tid] = o;

        carry += total;
        cur = nxt;
    }
}

extern "C" void kernel_launch(void* const* d_in, const int* in_sizes, int n_in,
                              void* d_out, int out_size)
{
    const float* x = (const float*)d_in[0];
    float*       y = (float*)d_out;
    const int total = in_sizes[0];
    const int rows  = total / T_LEN;   // 4096 for the reference shape

    cumavg_kernel<<<rows, THREADS>>>((const float4*)x, (float4*)y);
}

// round 4
// speedup vs baseline: 1.4144x; 1.3591x over previous
#include <cuda_runtime.h>
#include <cuda_bf16.h>

// CumAvgPool1d: y[..., t] = cumsum(x)[..., t] / (t+1)
// x: (8, 512, 16384) fp32 -> 4096 rows of T=16384.
//
// R3: warp-per-row, zero barriers. Row = 128 chunks of 128 elems; each lane
// owns one float4 per chunk (fully coalesced 512B warp accesses). Per chunk:
// register local scan + one warp shuffle-scan + lane31 broadcast carry.
// Depth-4 register prefetch ring keeps 2KB/warp of loads in flight,
// decoupled from the serial shuffle chain. Streaming cache hints (no reuse).

constexpr int T_LEN  = 16384;
constexpr int T_F4   = T_LEN / 4;     // 4096 float4 per row
constexpr int CHUNKS = 128;           // 128 elems per chunk
constexpr int WARPS_PER_CTA = 4;
constexpr int THREADS = WARPS_PER_CTA * 32;
constexpr int PF = 4;                 // prefetch depth (chunks)

__global__ void __launch_bounds__(THREADS)
cumavg_kernel(const float4* __restrict__ x, float4* __restrict__ y, int rows)
{
    const int lane = threadIdx.x & 31;
    const int warp = threadIdx.x >> 5;
    const int row  = blockIdx.x * WARPS_PER_CTA + warp;
    if (row >= rows) return;

    const float4* px = x + (size_t)row * T_F4;
    float4*       py = y + (size_t)row * T_F4;

    // prefetch ring: chunks 0..PF-1
    float4 buf[PF];
    #pragma unroll
    for (int i = 0; i < PF; ++i)
        buf[i] = __ldcs(px + i * 32 + lane);

    float carry = 0.0f;

    #pragma unroll 4
    for (int c = 0; c < CHUNKS; ++c) {
        float4 v = buf[c & (PF - 1)];
        // refill this slot with chunk c+PF (keeps PF chunk-loads in flight)
        if (c + PF < CHUNKS)
            buf[c & (PF - 1)] = __ldcs(px + (c + PF) * 32 + lane);

        // thread-local inclusive scan of 4 contiguous elements
        float r = v.x;  v.x = r;
        r += v.y;       v.y = r;
        r += v.z;       v.z = r;
        r += v.w;       v.w = r;

        // warp inclusive scan of per-lane totals
        float wval = r;
        #pragma unroll
        for (int d = 1; d < 32; d <<= 1) {
            float n = __shfl_up_sync(0xffffffffu, wval, d);
            if (lane >= d) wval += n;
        }

        const float off   = carry + (wval - r);              // exclusive prefix
        const float total = __shfl_sync(0xffffffffu, wval, 31);

        const int t0 = c * 128 + lane * 4;                   // global elem index
        float4 o;
        o.x = (off + v.x) * __fdividef(1.0f, (float)(t0 + 1));
        o.y = (off + v.y) * __fdividef(1.0f, (float)(t0 + 2));
        o.z = (off + v.z) * __fdividef(1.0f, (float)(t0 + 3));
        o.w = (off + v.w) * __fdividef(1.0f, (float)(t0 + 4));
        __stcs(py + c * 32 + lane, o);

        carry += total;
    }
}

extern "C" void kernel_launch(void* const* d_in, const int* in_sizes, int n_in,
                              void* d_out, int out_size)
{
    const float* x = (const float*)d_in[0];
    float*       y = (float*)d_out;
    const int total = in_sizes[0];
    const int rows  = total / T_LEN;   // 4096 for the reference shape

    const int ctas = (rows + WARPS_PER_CTA - 1) / WARPS_PER_CTA;
    cumavg_kernel<<<ctas, THREADS>>>((const float4*)x, (float4*)y, rows);
}